// round 13
// baseline (speedup 1.0000x reference)
#include <cuda_runtime.h>
#include <math.h>
#include <stdint.h>

#define B_   512
#define T_   128
#define N_   500
#define H_   1024
#define G3_  3072
#define BT_  65536
#define K2_  2048

typedef unsigned long long ull;

// ===================== static device scratch =====================
__device__ float g_xproj[(size_t)BT_ * G3_];
__device__ float g_seq  [(size_t)BT_ * H_];
__device__ float g_h0a  [B_ * H_];
__device__ float g_h0b  [B_ * H_];
__device__ float g_h1a  [B_ * H_];
__device__ float g_h1b  [B_ * H_];
__device__ float g_z    [B_ * H_];
__device__ float g_za   [B_ * H_];
__device__ float g_scores[B_ * N_];
__device__ float g_wih0p[(size_t)G3_ * N_];
__device__ float g_whh0p[(size_t)G3_ * H_];
__device__ float g_w1cat[(size_t)G3_ * K2_];   // row c = [wih1p_c | whh1p_c]
__device__ float g_bih0p[G3_];
__device__ float g_bhh0p[G3_];
__device__ float g_bih1p[G3_];
__device__ float g_bhh1p[G3_];
__device__ float g_bsum1[G3_];                 // bih1p + bhh1p

// ===================== helpers =====================
__device__ __forceinline__ ull pack2(float lo, float hi) {
    ull r; asm("mov.b64 %0, {%1, %2};" : "=l"(r) : "f"(lo), "f"(hi)); return r;
}
__device__ __forceinline__ float2 unpack2(ull v) {
    float2 r; asm("mov.b64 {%0, %1}, %2;" : "=f"(r.x), "=f"(r.y) : "l"(v)); return r;
}
__device__ __forceinline__ void ffma2(ull& d, ull a, ull b) {
    asm("fma.rn.f32x2 %0, %1, %2, %3;" : "=l"(d) : "l"(a), "l"(b), "l"(d));
}
__device__ __forceinline__ float sigf(float x) { return 1.f / (1.f + __expf(-x)); }

#define BM 128
#define BN 96
#define BK 16
#define NT 256

// ===================== R2-verbatim loaders =====================
__device__ __forceinline__ void load_tileA(const float* __restrict__ A, int M, int K,
                                           int m0, int k0, int am, int ak, float4* Apre)
{
    #pragma unroll
    for (int r = 0; r < 2; r++) {
        int gm = m0 + am + r * 64;
        int gk = k0 + ak;
        float4 v = make_float4(0.f, 0.f, 0.f, 0.f);
        if (gm < M) {
            if (gk + 3 < K) v = *(const float4*)(A + (size_t)gm * K + gk);
            else {
                if (gk + 0 < K) v.x = A[(size_t)gm * K + gk + 0];
                if (gk + 1 < K) v.y = A[(size_t)gm * K + gk + 1];
                if (gk + 2 < K) v.z = A[(size_t)gm * K + gk + 2];
                if (gk + 3 < K) v.w = A[(size_t)gm * K + gk + 3];
            }
        }
        Apre[r] = v;
    }
}
__device__ __forceinline__ void load_tileB(const float* __restrict__ Bm, int Nd, int K,
                                           int n0, int k0, int tid, float2* Bpre)
{
    #pragma unroll
    for (int j = 0; j < 3; j++) {
        int i2 = tid + j * 256;
        int bn = i2 >> 3;
        int bk = (i2 & 7) << 1;
        int gn = n0 + bn, gk = k0 + bk;
        float2 v = make_float2(0.f, 0.f);
        if (gn < Nd && gk < K) v = *(const float2*)(Bm + (size_t)gn * K + gk);
        Bpre[j] = v;
    }
}
// strided A loader (row stride in elems, no guards — always in-bounds/aligned)
__device__ __forceinline__ void load_tileA_s(const float* __restrict__ A, size_t strideE,
                                             int m0, int k0, int am, int ak, float4* Apre)
{
    #pragma unroll
    for (int r = 0; r < 2; r++)
        Apre[r] = *(const float4*)(A + (size_t)(m0 + am + r * 64) * strideE + k0 + ak);
}

// ===================== R2-verbatim projection GEMM =====================
__global__ __launch_bounds__(NT)
void gemm_f2(const float* __restrict__ A, const float* __restrict__ Bm,
             const float* __restrict__ bias, float* __restrict__ C,
             int M, int Nd, int K)
{
    __shared__ float As[BK][BM + 4];
    __shared__ float Bs[BK][BN + 2];
    const int tid = threadIdx.x;
    const int tx = tid & 15, ty = tid >> 4;
    const int m0 = blockIdx.y * BM, n0 = blockIdx.x * BN;
    const int am = tid >> 2;
    const int ak = (tid & 3) << 2;
    ull acc[4][6];
    #pragma unroll
    for (int i = 0; i < 4; i++)
        #pragma unroll
        for (int j = 0; j < 6; j++) acc[i][j] = 0ull;
    float4 Apre[2]; float2 Bpre[3];
    const int ntiles = (K + BK - 1) / BK;
    load_tileA(A, M, K, m0, 0, am, ak, Apre);
    load_tileB(Bm, Nd, K, n0, 0, tid, Bpre);
    for (int kt = 0; kt < ntiles; kt++) {
        #pragma unroll
        for (int r = 0; r < 2; r++) {
            As[ak + 0][am + r * 64] = Apre[r].x;
            As[ak + 1][am + r * 64] = Apre[r].y;
            As[ak + 2][am + r * 64] = Apre[r].z;
            As[ak + 3][am + r * 64] = Apre[r].w;
        }
        #pragma unroll
        for (int j = 0; j < 3; j++) {
            int i2 = tid + j * 256;
            int bn = i2 >> 3, bk = (i2 & 7) << 1;
            Bs[bk][bn]     = Bpre[j].x;
            Bs[bk + 1][bn] = Bpre[j].y;
        }
        __syncthreads();
        if (kt + 1 < ntiles) {
            load_tileA(A, M, K, m0, (kt + 1) * BK, am, ak, Apre);
            load_tileB(Bm, Nd, K, n0, (kt + 1) * BK, tid, Bpre);
        }
        #pragma unroll
        for (int k = 0; k < BK; k++) {
            ull av[4];
            #pragma unroll
            for (int i = 0; i < 4; i++) av[i] = *(const ull*)&As[k][ty * 8 + 2 * i];
            ull bv[6];
            #pragma unroll
            for (int j = 0; j < 6; j++) { float b = Bs[k][tx * 6 + j]; bv[j] = pack2(b, b); }
            #pragma unroll
            for (int i = 0; i < 4; i++)
                #pragma unroll
                for (int j = 0; j < 6; j++) ffma2(acc[i][j], av[i], bv[j]);
        }
        __syncthreads();
    }
    #pragma unroll
    for (int i = 0; i < 4; i++) {
        int gm0 = m0 + ty * 8 + 2 * i;
        #pragma unroll
        for (int j = 0; j < 6; j++) {
            int gn = n0 + tx * 6 + j;
            if (gn >= Nd) continue;
            float2 v = unpack2(acc[i][j]);
            float bb = bias ? bias[gn] : 0.f;
            if (gm0 < M)     C[(size_t)gm0 * Nd + gn]       = v.x + bb;
            if (gm0 + 1 < M) C[(size_t)(gm0 + 1) * Nd + gn] = v.y + bb;
        }
    }
}

// ===================== paired recurrence step =====================
// z==0: layer-0 step t   (R2 path: K=1024 GEMM vs whh0p, gates with xproj)
// z==1: layer-1 step t-1 (K=2048 GEMM vs w1cat over [seq_{t-1} | h1];
//        n-gate h-part kept in separate accumulators)
__global__ __launch_bounds__(NT, 2)
void gru_pair(const float* __restrict__ h0in, float* __restrict__ h0out,
              const float* __restrict__ xp,  float* __restrict__ seqp,
              const float* __restrict__ whh0, const float* __restrict__ bhh0,
              const float* __restrict__ w1cat,
              const float* __restrict__ bih1, const float* __restrict__ bhh1,
              const float* __restrict__ bsum1,
              const float* __restrict__ h1in, float* __restrict__ h1out,
              int t)
{
    __shared__ float As[BK][BM + 4];
    __shared__ float Bs[BK][BN + 2];
    const int tid = threadIdx.x;
    const int tx = tid & 15, ty = tid >> 4;
    const int m0 = blockIdx.y * BM, n0 = blockIdx.x * BN;
    const int am = tid >> 2;
    const int ak = (tid & 3) << 2;

    if (blockIdx.z == 0) {
        // ---------------- layer-0: R2 path ----------------
        if (t >= T_) return;
        ull acc[4][6];
        #pragma unroll
        for (int i = 0; i < 4; i++)
            #pragma unroll
            for (int j = 0; j < 6; j++) acc[i][j] = 0ull;
        float4 Apre[2]; float2 Bpre[3];
        const int ntiles = H_ / BK;
        load_tileA_s(h0in, H_, m0, 0, am, ak, Apre);
        load_tileB(whh0, G3_, H_, n0, 0, tid, Bpre);
        for (int kt = 0; kt < ntiles; kt++) {
            #pragma unroll
            for (int r = 0; r < 2; r++) {
                As[ak + 0][am + r * 64] = Apre[r].x;
                As[ak + 1][am + r * 64] = Apre[r].y;
                As[ak + 2][am + r * 64] = Apre[r].z;
                As[ak + 3][am + r * 64] = Apre[r].w;
            }
            #pragma unroll
            for (int j = 0; j < 3; j++) {
                int i2 = tid + j * 256;
                int bn = i2 >> 3, bk = (i2 & 7) << 1;
                Bs[bk][bn]     = Bpre[j].x;
                Bs[bk + 1][bn] = Bpre[j].y;
            }
            __syncthreads();
            if (kt + 1 < ntiles) {
                load_tileA_s(h0in, H_, m0, (kt + 1) * BK, am, ak, Apre);
                load_tileB(whh0, G3_, H_, n0, (kt + 1) * BK, tid, Bpre);
            }
            #pragma unroll
            for (int k = 0; k < BK; k++) {
                ull av[4];
                #pragma unroll
                for (int i = 0; i < 4; i++) av[i] = *(const ull*)&As[k][ty * 8 + 2 * i];
                ull bv[6];
                #pragma unroll
                for (int j = 0; j < 6; j++) { float b = Bs[k][tx * 6 + j]; bv[j] = pack2(b, b); }
                #pragma unroll
                for (int i = 0; i < 4; i++)
                    #pragma unroll
                    for (int j = 0; j < 6; j++) ffma2(acc[i][j], av[i], bv[j]);
            }
            __syncthreads();
        }
        const int col0 = n0 + tx * 6;
        const int hu0  = col0 / 3;
        #pragma unroll
        for (int i = 0; i < 4; i++) {
            int b0 = m0 + ty * 8 + 2 * i;
            float ga[6], gb[6];
            #pragma unroll
            for (int j = 0; j < 6; j++) {
                float2 v = unpack2(acc[i][j]);
                ga[j] = v.x + bhh0[col0 + j];
                gb[j] = v.y + bhh0[col0 + j];
            }
            #pragma unroll
            for (int e = 0; e < 2; e++) {
                int b = b0 + e;
                const float* gg = e ? gb : ga;
                const float* xr = xp + ((size_t)b * T_ + t) * G3_ + col0;
                #pragma unroll
                for (int u = 0; u < 2; u++) {
                    int c  = 3 * u;
                    int hu = hu0 + u;
                    float r  = sigf(xr[c + 0] + gg[c + 0]);
                    float z  = sigf(xr[c + 1] + gg[c + 1]);
                    float nn = tanhf(xr[c + 2] + r * gg[c + 2]);
                    float hp = h0in[(size_t)b * H_ + hu];
                    float hv = (1.f - z) * nn + z * hp;
                    h0out[(size_t)b * H_ + hu] = hv;
                    seqp[((size_t)b * T_ + t) * H_ + hu] = hv;
                }
            }
        }
    } else {
        // ---------------- layer-1: fused proj + recurrence, step t1 = t-1 ------
        const int t1 = t - 1;
        if (t1 < 0) return;
        ull acc[4][6];   // r,z: x+h combined; n: x-part only
        ull accn[4][2];  // n: h-part
        #pragma unroll
        for (int i = 0; i < 4; i++) {
            #pragma unroll
            for (int j = 0; j < 6; j++) acc[i][j] = 0ull;
            accn[i][0] = 0ull; accn[i][1] = 0ull;
        }
        const float* A0 = g_seq + (size_t)t1 * H_;   // row stride T_*H_
        float4 Apre[2]; float2 Bpre[3];
        const int half = H_ / BK;                     // 64 tiles per phase

        load_tileA_s(A0, (size_t)T_ * H_, m0, 0, am, ak, Apre);
        load_tileB(w1cat, G3_, K2_, n0, 0, tid, Bpre);

        // ---- phase 0: x-part (K 0..1023), all cols -> acc ----
        for (int kt = 0; kt < half; kt++) {
            #pragma unroll
            for (int r = 0; r < 2; r++) {
                As[ak + 0][am + r * 64] = Apre[r].x;
                As[ak + 1][am + r * 64] = Apre[r].y;
                As[ak + 2][am + r * 64] = Apre[r].z;
                As[ak + 3][am + r * 64] = Apre[r].w;
            }
            #pragma unroll
            for (int j = 0; j < 3; j++) {
                int i2 = tid + j * 256;
                int bn = i2 >> 3, bk = (i2 & 7) << 1;
                Bs[bk][bn]     = Bpre[j].x;
                Bs[bk + 1][bn] = Bpre[j].y;
            }
            __syncthreads();
            if (kt + 1 < half) load_tileA_s(A0, (size_t)T_ * H_, m0, (kt + 1) * BK, am, ak, Apre);
            else               load_tileA_s(h1in, H_, m0, 0, am, ak, Apre);
            load_tileB(w1cat, G3_, K2_, n0, (kt + 1) * BK, tid, Bpre);
            #pragma unroll
            for (int k = 0; k < BK; k++) {
                ull av[4];
                #pragma unroll
                for (int i = 0; i < 4; i++) av[i] = *(const ull*)&As[k][ty * 8 + 2 * i];
                ull bv[6];
                #pragma unroll
                for (int j = 0; j < 6; j++) { float b = Bs[k][tx * 6 + j]; bv[j] = pack2(b, b); }
                #pragma unroll
                for (int i = 0; i < 4; i++)
                    #pragma unroll
                    for (int j = 0; j < 6; j++) ffma2(acc[i][j], av[i], bv[j]);
            }
            __syncthreads();
        }
        // ---- phase 1: h-part (K 1024..2047); n-cols -> accn ----
        for (int kt = 0; kt < half; kt++) {
            #pragma unroll
            for (int r = 0; r < 2; r++) {
                As[ak + 0][am + r * 64] = Apre[r].x;
                As[ak + 1][am + r * 64] = Apre[r].y;
                As[ak + 2][am + r * 64] = Apre[r].z;
                As[ak + 3][am + r * 64] = Apre[r].w;
            }
            #pragma unroll
            for (int j = 0; j < 3; j++) {
                int i2 = tid + j * 256;
                int bn = i2 >> 3, bk = (i2 & 7) << 1;
                Bs[bk][bn]     = Bpre[j].x;
                Bs[bk + 1][bn] = Bpre[j].y;
            }
            __syncthreads();
            if (kt + 1 < half) {
                load_tileA_s(h1in, H_, m0, (kt + 1) * BK, am, ak, Apre);
                load_tileB(w1cat, G3_, K2_, n0, (half + kt + 1) * BK, tid, Bpre);
            }
            #pragma unroll
            for (int k = 0; k < BK; k++) {
                ull av[4];
                #pragma unroll
                for (int i = 0; i < 4; i++) av[i] = *(const ull*)&As[k][ty * 8 + 2 * i];
                ull bv[6];
                #pragma unroll
                for (int j = 0; j < 6; j++) { float b = Bs[k][tx * 6 + j]; bv[j] = pack2(b, b); }
                #pragma unroll
                for (int i = 0; i < 4; i++) {
                    ffma2(acc[i][0],  av[i], bv[0]);
                    ffma2(acc[i][1],  av[i], bv[1]);
                    ffma2(accn[i][0], av[i], bv[2]);   // n of triple 0
                    ffma2(acc[i][3],  av[i], bv[3]);
                    ffma2(acc[i][4],  av[i], bv[4]);
                    ffma2(accn[i][1], av[i], bv[5]);   // n of triple 1
                }
            }
            __syncthreads();
        }
        // ---- gate epilogue ----
        const int col0 = n0 + tx * 6;
        const int hu0  = col0 / 3;
        #pragma unroll
        for (int i = 0; i < 4; i++) {
            int b0 = m0 + ty * 8 + 2 * i;
            #pragma unroll
            for (int e = 0; e < 2; e++) {
                int b = b0 + e;
                #pragma unroll
                for (int u = 0; u < 2; u++) {
                    int jr = 3 * u, jz = 3 * u + 1, jn = 3 * u + 2;
                    float2 vr = unpack2(acc[i][jr]);
                    float2 vz = unpack2(acc[i][jz]);
                    float2 vx = unpack2(acc[i][jn]);
                    float2 vh = unpack2(accn[i][u]);
                    float sr = (e ? vr.y : vr.x) + bsum1[col0 + jr];
                    float sz = (e ? vz.y : vz.x) + bsum1[col0 + jz];
                    float xn = (e ? vx.y : vx.x) + bih1[col0 + jn];
                    float hn = (e ? vh.y : vh.x) + bhh1[col0 + jn];
                    float r  = sigf(sr);
                    float z  = sigf(sz);
                    float nn = tanhf(xn + r * hn);
                    int hu = hu0 + u;
                    float hp = h1in[(size_t)b * H_ + hu];
                    float hv = (1.f - z) * nn + z * hp;
                    h1out[(size_t)b * H_ + hu] = hv;
                }
            }
        }
    }
}

// ===================== misc kernels =====================
__global__ void permute_w(const float* __restrict__ w, float* __restrict__ wp, int K)
{
    int c = blockIdx.y;
    int k = blockIdx.x * 256 + threadIdx.x;
    if (k >= K) return;
    int g = c % 3, h = c / 3;
    wp[(size_t)c * K + k] = w[(size_t)(g * H_ + h) * K + k];
}
// concat permute: dst row c (stride 2048), cols [off, off+1024) from src row (g*H+h)
__global__ void permute_cat(const float* __restrict__ w, float* __restrict__ dst, int off)
{
    int c = blockIdx.y;
    int k = blockIdx.x * 256 + threadIdx.x;
    if (k >= H_) return;
    int g = c % 3, h = c / 3;
    dst[(size_t)c * K2_ + off + k] = w[(size_t)(g * H_ + h) * H_ + k];
}
__global__ void permute_b(const float* __restrict__ b, float* __restrict__ bp)
{
    int c = blockIdx.x * 256 + threadIdx.x;
    if (c < G3_) bp[c] = b[(c % 3) * H_ + c / 3];
}
__global__ void bias_sum(const float* __restrict__ a, const float* __restrict__ b,
                         float* __restrict__ s)
{
    int c = blockIdx.x * 256 + threadIdx.x;
    if (c < G3_) s[c] = a[c] + b[c];
}
__global__ void zero_kernel(float* __restrict__ p, int n)
{
    int i = blockIdx.x * blockDim.x + threadIdx.x;
    if (i < n) p[i] = 0.f;
}

__global__ __launch_bounds__(256)
void ln_silu(const float* __restrict__ z,
             const float* __restrict__ lng,
             const float* __restrict__ lnb,
             float* __restrict__ out)
{
    __shared__ float red[256];
    int b = blockIdx.x, tid = threadIdx.x;
    const float* row = z + (size_t)b * H_;
    float s = 0.f, s2 = 0.f;
    for (int i = tid; i < H_; i += 256) { float v = row[i]; s += v; s2 += v * v; }
    red[tid] = s; __syncthreads();
    for (int o = 128; o > 0; o >>= 1) { if (tid < o) red[tid] += red[tid + o]; __syncthreads(); }
    float mu = red[0] / H_;
    __syncthreads();
    red[tid] = s2; __syncthreads();
    for (int o = 128; o > 0; o >>= 1) { if (tid < o) red[tid] += red[tid + o]; __syncthreads(); }
    float var = red[0] / H_ - mu * mu;
    float inv = rsqrtf(var + 1e-5f);
    for (int i = tid; i < H_; i += 256) {
        float y = (row[i] - mu) * inv * lng[i] + lnb[i];
        out[(size_t)b * H_ + i] = y / (1.f + expf(-y));
    }
}

__global__ __launch_bounds__(512)
void softmax_rebalance(const float* __restrict__ scores,
                       float* __restrict__ out)
{
    __shared__ float red[512];
    int b = blockIdx.x, tid = threadIdx.x;
    float s = (tid < N_) ? scores[(size_t)b * N_ + tid] : -INFINITY;
    if (s < 0.f) s = -INFINITY;
    red[tid] = s; __syncthreads();
    for (int o = 256; o > 0; o >>= 1) { if (tid < o) red[tid] = fmaxf(red[tid], red[tid + o]); __syncthreads(); }
    float m = red[0]; __syncthreads();
    float e = (tid < N_) ? expf(s - m) : 0.f;
    red[tid] = e; __syncthreads();
    for (int o = 256; o > 0; o >>= 1) { if (tid < o) red[tid] += red[tid + o]; __syncthreads(); }
    float S = red[0]; __syncthreads();
    float w = e / S;
    w = fminf(fmaxf(w, 0.0f), 0.1f);
    for (int it = 0; it < 20; it++) {
        red[tid] = (tid < N_) ? w : 0.f; __syncthreads();
        for (int o = 256; o > 0; o >>= 1) { if (tid < o) red[tid] += red[tid + o]; __syncthreads(); }
        float tot = red[0]; __syncthreads();
        float excess = tot - 1.0f;
        bool  active = excess > 1e-6f;
        float sur = fmaxf(w - 0.1f, 0.f);
        red[tid] = (tid < N_) ? sur : 0.f; __syncthreads();
        for (int o = 256; o > 0; o >>= 1) { if (tid < o) red[tid] += red[tid + o]; __syncthreads(); }
        float totsur = red[0]; __syncthreads();
        float upd = (totsur > 0.f)
                  ? w - sur / fmaxf(totsur, 1e-12f) * excess
                  : w - excess / (float)N_;
        upd = fminf(fmaxf(upd, 0.0f), 0.1f);
        if (active) w = upd;
    }
    if (tid < N_) out[(size_t)b * N_ + tid] = w;
}

// ===================== orchestration =====================
extern "C" void kernel_launch(void* const* d_in, const int* in_sizes, int n_in,
                              void* d_out, int out_size)
{
    const float* x     = (const float*)d_in[0];
    const float* w_ih0 = (const float*)d_in[1];
    const float* w_hh0 = (const float*)d_in[2];
    const float* b_ih0 = (const float*)d_in[3];
    const float* b_hh0 = (const float*)d_in[4];
    const float* w_ih1 = (const float*)d_in[5];
    const float* w_hh1 = (const float*)d_in[6];
    const float* b_ih1 = (const float*)d_in[7];
    const float* b_hh1 = (const float*)d_in[8];
    const float* w1    = (const float*)d_in[9];
    const float* b1    = (const float*)d_in[10];
    const float* ln_g  = (const float*)d_in[11];
    const float* ln_b  = (const float*)d_in[12];
    const float* w2    = (const float*)d_in[13];
    const float* b2    = (const float*)d_in[14];
    float* out = (float*)d_out;

    void* p;
    float *xproj, *seq, *h0a, *h0b, *h1a, *h1b, *z, *za, *scores;
    float *wih0p, *whh0p, *w1cat, *bih0p, *bhh0p, *bih1p, *bhh1p, *bsum1;
    cudaGetSymbolAddress(&p, g_xproj);  xproj  = (float*)p;
    cudaGetSymbolAddress(&p, g_seq);    seq    = (float*)p;
    cudaGetSymbolAddress(&p, g_h0a);    h0a    = (float*)p;
    cudaGetSymbolAddress(&p, g_h0b);    h0b    = (float*)p;
    cudaGetSymbolAddress(&p, g_h1a);    h1a    = (float*)p;
    cudaGetSymbolAddress(&p, g_h1b);    h1b    = (float*)p;
    cudaGetSymbolAddress(&p, g_z);      z      = (float*)p;
    cudaGetSymbolAddress(&p, g_za);     za     = (float*)p;
    cudaGetSymbolAddress(&p, g_scores); scores = (float*)p;
    cudaGetSymbolAddress(&p, g_wih0p);  wih0p  = (float*)p;
    cudaGetSymbolAddress(&p, g_whh0p);  whh0p  = (float*)p;
    cudaGetSymbolAddress(&p, g_w1cat);  w1cat  = (float*)p;
    cudaGetSymbolAddress(&p, g_bih0p);  bih0p  = (float*)p;
    cudaGetSymbolAddress(&p, g_bhh0p);  bhh0p  = (float*)p;
    cudaGetSymbolAddress(&p, g_bih1p);  bih1p  = (float*)p;
    cudaGetSymbolAddress(&p, g_bhh1p);  bhh1p  = (float*)p;
    cudaGetSymbolAddress(&p, g_bsum1);  bsum1  = (float*)p;

    // permutations
    permute_w<<<dim3((N_ + 255) / 256, G3_), 256>>>(w_ih0, wih0p, N_);
    permute_w<<<dim3((H_ + 255) / 256, G3_), 256>>>(w_hh0, whh0p, H_);
    permute_cat<<<dim3((H_ + 255) / 256, G3_), 256>>>(w_ih1, w1cat, 0);
    permute_cat<<<dim3((H_ + 255) / 256, G3_), 256>>>(w_hh1, w1cat, H_);
    permute_b<<<(G3_ + 255) / 256, 256>>>(b_ih0, bih0p);
    permute_b<<<(G3_ + 255) / 256, 256>>>(b_hh0, bhh0p);
    permute_b<<<(G3_ + 255) / 256, 256>>>(b_ih1, bih1p);
    permute_b<<<(G3_ + 255) / 256, 256>>>(b_hh1, bhh1p);
    bias_sum<<<(G3_ + 255) / 256, 256>>>(bih1p, bhh1p, bsum1);

    // layer-0 input projection
    gemm_f2<<<dim3(G3_ / BN, BT_ / BM), NT>>>(x, wih0p, bih0p, xproj, BT_, G3_, N_);
    zero_kernel<<<(B_ * H_ + 255) / 256, 256>>>(h0a, B_ * H_);
    zero_kernel<<<(B_ * H_ + 255) / 256, 256>>>(h1a, B_ * H_);

    // skewed pipeline: launch L_t runs layer0(t) [z=0] and layer1(t-1) [z=1]
    for (int t = 0; t <= T_; t++) {
        float* h0in  = (t & 1) ? h0b : h0a;
        float* h0out = (t & 1) ? h0a : h0b;
        int t1 = t - 1;
        float* h1in  = (t1 & 1) ? h1b : h1a;
        float* h1out = (t1 & 1) ? h1a : h1b;
        gru_pair<<<dim3(G3_ / BN, B_ / BM, 2), NT>>>(
            h0in, h0out, xproj, seq,
            whh0p, bhh0p,
            w1cat, bih1p, bhh1p, bsum1,
            h1in, h1out, t);
    }
    // final h1: t1 = 127 (odd) -> h1out = h1a

    // head
    gemm_f2<<<dim3((H_ + BN - 1) / BN, B_ / BM), NT>>>(h1a, w1, b1, z, B_, H_, H_);
    ln_silu<<<B_, 256>>>(z, ln_g, ln_b, za);
    gemm_f2<<<dim3((N_ + BN - 1) / BN, B_ / BM), NT>>>(za, w2, b2, scores, B_, N_, H_);
    softmax_rebalance<<<B_, 512>>>(scores, out);
}

// round 14
// speedup vs baseline: 2.3674x; 2.3674x over previous
#include <cuda_runtime.h>
#include <math.h>
#include <stdint.h>

#define B_   512
#define T_   128
#define N_   500
#define H_   1024
#define G3_  3072
#define BT_  65536

typedef unsigned long long ull;

// ===================== static device scratch =====================
__device__ float g_xproj[(size_t)BT_ * G3_];
__device__ float g_seq  [(size_t)BT_ * H_];
__device__ float g_h0   [B_ * H_];
__device__ float g_h1   [B_ * H_];
__device__ float g_z    [B_ * H_];
__device__ float g_za   [B_ * H_];
__device__ float g_scores[B_ * N_];
__device__ float g_wih0p[(size_t)G3_ * N_];
__device__ float g_whh0p[(size_t)G3_ * H_];
__device__ float g_wih1p[(size_t)G3_ * H_];
__device__ float g_whh1p[(size_t)G3_ * H_];
__device__ float g_bih0p[G3_];
__device__ float g_bhh0p[G3_];
__device__ float g_bih1p[G3_];
__device__ float g_bhh1p[G3_];

// ===================== helpers =====================
__device__ __forceinline__ ull pack2(float lo, float hi) {
    ull r; asm("mov.b64 %0, {%1, %2};" : "=l"(r) : "f"(lo), "f"(hi)); return r;
}
__device__ __forceinline__ float2 unpack2(ull v) {
    float2 r; asm("mov.b64 {%0, %1}, %2;" : "=f"(r.x), "=f"(r.y) : "l"(v)); return r;
}
__device__ __forceinline__ void ffma2(ull& d, ull a, ull b) {
    asm("fma.rn.f32x2 %0, %1, %2, %3;" : "=l"(d) : "l"(a), "l"(b), "l"(d));
}
__device__ __forceinline__ float sigf(float x) { return 1.f / (1.f + __expf(-x)); }

#define BM 128
#define BN 96
#define BK 16
#define NT 256

// ===================== guarded loaders (projections / head) =====================
__device__ __forceinline__ void load_tileA(const float* __restrict__ A, int M, int K,
                                           int m0, int k0, int am, int ak, float4* Apre)
{
    #pragma unroll
    for (int r = 0; r < 2; r++) {
        int gm = m0 + am + r * 64;
        int gk = k0 + ak;
        float4 v = make_float4(0.f, 0.f, 0.f, 0.f);
        if (gm < M) {
            if (gk + 3 < K) v = *(const float4*)(A + (size_t)gm * K + gk);
            else {
                if (gk + 0 < K) v.x = A[(size_t)gm * K + gk + 0];
                if (gk + 1 < K) v.y = A[(size_t)gm * K + gk + 1];
                if (gk + 2 < K) v.z = A[(size_t)gm * K + gk + 2];
                if (gk + 3 < K) v.w = A[(size_t)gm * K + gk + 3];
            }
        }
        Apre[r] = v;
    }
}
__device__ __forceinline__ void load_tileB(const float* __restrict__ Bm, int Nd, int K,
                                           int n0, int k0, int tid, float2* Bpre)
{
    #pragma unroll
    for (int j = 0; j < 3; j++) {
        int i2 = tid + j * 256;
        int bn = i2 >> 3;
        int bk = (i2 & 7) << 1;
        int gn = n0 + bn, gk = k0 + bk;
        float2 v = make_float2(0.f, 0.f);
        if (gn < Nd && gk < K) v = *(const float2*)(Bm + (size_t)gn * K + gk);
        Bpre[j] = v;
    }
}
// unguarded loaders (recurrence: all indices statically in-bounds)
__device__ __forceinline__ void load_tileA_u(const float* __restrict__ A,
                                             int m0, int k0, int am, int ak, float4* Apre)
{
    #pragma unroll
    for (int r = 0; r < 2; r++)
        Apre[r] = *(const float4*)(A + (size_t)(m0 + am + r * 64) * H_ + k0 + ak);
}
__device__ __forceinline__ void load_tileB_u(const float* __restrict__ Bm,
                                             int n0, int k0, int tid, float2* Bpre)
{
    #pragma unroll
    for (int j = 0; j < 3; j++) {
        int i2 = tid + j * 256;
        int bn = i2 >> 3;
        int bk = (i2 & 7) << 1;
        Bpre[j] = *(const float2*)(Bm + (size_t)(n0 + bn) * H_ + k0 + bk);
    }
}

// ===================== R2-verbatim projection/head GEMM =====================
__global__ __launch_bounds__(NT)
void gemm_f2(const float* __restrict__ A, const float* __restrict__ Bm,
             const float* __restrict__ bias, float* __restrict__ C,
             int M, int Nd, int K)
{
    __shared__ float As[BK][BM + 4];
    __shared__ float Bs[BK][BN + 2];
    const int tid = threadIdx.x;
    const int tx = tid & 15, ty = tid >> 4;
    const int m0 = blockIdx.y * BM, n0 = blockIdx.x * BN;
    const int am = tid >> 2;
    const int ak = (tid & 3) << 2;
    ull acc[4][6];
    #pragma unroll
    for (int i = 0; i < 4; i++)
        #pragma unroll
        for (int j = 0; j < 6; j++) acc[i][j] = 0ull;
    float4 Apre[2]; float2 Bpre[3];
    const int ntiles = (K + BK - 1) / BK;
    load_tileA(A, M, K, m0, 0, am, ak, Apre);
    load_tileB(Bm, Nd, K, n0, 0, tid, Bpre);
    for (int kt = 0; kt < ntiles; kt++) {
        #pragma unroll
        for (int r = 0; r < 2; r++) {
            As[ak + 0][am + r * 64] = Apre[r].x;
            As[ak + 1][am + r * 64] = Apre[r].y;
            As[ak + 2][am + r * 64] = Apre[r].z;
            As[ak + 3][am + r * 64] = Apre[r].w;
        }
        #pragma unroll
        for (int j = 0; j < 3; j++) {
            int i2 = tid + j * 256;
            int bn = i2 >> 3, bk = (i2 & 7) << 1;
            Bs[bk][bn]     = Bpre[j].x;
            Bs[bk + 1][bn] = Bpre[j].y;
        }
        __syncthreads();
        if (kt + 1 < ntiles) {
            load_tileA(A, M, K, m0, (kt + 1) * BK, am, ak, Apre);
            load_tileB(Bm, Nd, K, n0, (kt + 1) * BK, tid, Bpre);
        }
        #pragma unroll
        for (int k = 0; k < BK; k++) {
            ull av[4];
            #pragma unroll
            for (int i = 0; i < 4; i++) av[i] = *(const ull*)&As[k][ty * 8 + 2 * i];
            ull bv[6];
            #pragma unroll
            for (int j = 0; j < 6; j++) { float b = Bs[k][tx * 6 + j]; bv[j] = pack2(b, b); }
            #pragma unroll
            for (int i = 0; i < 4; i++)
                #pragma unroll
                for (int j = 0; j < 6; j++) ffma2(acc[i][j], av[i], bv[j]);
        }
        __syncthreads();
    }
    #pragma unroll
    for (int i = 0; i < 4; i++) {
        int gm0 = m0 + ty * 8 + 2 * i;
        #pragma unroll
        for (int j = 0; j < 6; j++) {
            int gn = n0 + tx * 6 + j;
            if (gn >= Nd) continue;
            float2 v = unpack2(acc[i][j]);
            float bb = bias ? bias[gn] : 0.f;
            if (gm0 < M)     C[(size_t)gm0 * Nd + gn]       = v.x + bb;
            if (gm0 + 1 < M) C[(size_t)(gm0 + 1) * Nd + gn] = v.y + bb;
        }
    }
}

// ===================== recurrence: R2 structure, unguarded loads =====================
__global__ __launch_bounds__(NT)
void gru_step(const float* __restrict__ hin, const float* __restrict__ W,
              const float* __restrict__ bias, const float* __restrict__ xp,
              float* __restrict__ hout, float* __restrict__ seqp, int t)
{
    __shared__ float As[BK][BM + 4];
    __shared__ float Bs[BK][BN + 2];
    const int tid = threadIdx.x;
    const int tx = tid & 15, ty = tid >> 4;
    const int m0 = blockIdx.y * BM, n0 = blockIdx.x * BN;
    const int am = tid >> 2;
    const int ak = (tid & 3) << 2;
    ull acc[4][6];
    #pragma unroll
    for (int i = 0; i < 4; i++)
        #pragma unroll
        for (int j = 0; j < 6; j++) acc[i][j] = 0ull;
    float4 Apre[2]; float2 Bpre[3];
    const int ntiles = H_ / BK;       // 64
    load_tileA_u(hin, m0, 0, am, ak, Apre);
    load_tileB_u(W, n0, 0, tid, Bpre);
    for (int kt = 0; kt < ntiles; kt++) {
        #pragma unroll
        for (int r = 0; r < 2; r++) {
            As[ak + 0][am + r * 64] = Apre[r].x;
            As[ak + 1][am + r * 64] = Apre[r].y;
            As[ak + 2][am + r * 64] = Apre[r].z;
            As[ak + 3][am + r * 64] = Apre[r].w;
        }
        #pragma unroll
        for (int j = 0; j < 3; j++) {
            int i2 = tid + j * 256;
            int bn = i2 >> 3, bk = (i2 & 7) << 1;
            Bs[bk][bn]     = Bpre[j].x;
            Bs[bk + 1][bn] = Bpre[j].y;
        }
        __syncthreads();
        if (kt + 1 < ntiles) {
            load_tileA_u(hin, m0, (kt + 1) * BK, am, ak, Apre);
            load_tileB_u(W, n0, (kt + 1) * BK, tid, Bpre);
        }
        #pragma unroll
        for (int k = 0; k < BK; k++) {
            ull av[4];
            #pragma unroll
            for (int i = 0; i < 4; i++) av[i] = *(const ull*)&As[k][ty * 8 + 2 * i];
            ull bv[6];
            #pragma unroll
            for (int j = 0; j < 6; j++) { float b = Bs[k][tx * 6 + j]; bv[j] = pack2(b, b); }
            #pragma unroll
            for (int i = 0; i < 4; i++)
                #pragma unroll
                for (int j = 0; j < 6; j++) ffma2(acc[i][j], av[i], bv[j]);
        }
        __syncthreads();
    }

    const int col0 = n0 + tx * 6;      // two complete gate triples
    const int hu0  = col0 / 3;
    #pragma unroll
    for (int i = 0; i < 4; i++) {
        int b0 = m0 + ty * 8 + 2 * i;
        float ga[6], gb[6];
        #pragma unroll
        for (int j = 0; j < 6; j++) {
            float2 v = unpack2(acc[i][j]);
            ga[j] = v.x + bias[col0 + j];
            gb[j] = v.y + bias[col0 + j];
        }
        #pragma unroll
        for (int e = 0; e < 2; e++) {
            int b = b0 + e;
            const float* gg = e ? gb : ga;
            const float* xr = xp + ((size_t)b * T_ + t) * G3_ + col0;
            #pragma unroll
            for (int u = 0; u < 2; u++) {
                int c  = 3 * u;
                int hu = hu0 + u;
                float r  = sigf(xr[c + 0] + gg[c + 0]);
                float z  = sigf(xr[c + 1] + gg[c + 1]);
                float nn = tanhf(xr[c + 2] + r * gg[c + 2]);
                float hp = hin[(size_t)b * H_ + hu];
                float hv = (1.f - z) * nn + z * hp;
                hout[(size_t)b * H_ + hu] = hv;
                if (seqp) seqp[((size_t)b * T_ + t) * H_ + hu] = hv;
            }
        }
    }
}

// ===================== misc kernels =====================
__global__ void permute_w(const float* __restrict__ w, float* __restrict__ wp, int K)
{
    int c = blockIdx.y;
    int k = blockIdx.x * 256 + threadIdx.x;
    if (k >= K) return;
    int g = c % 3, h = c / 3;
    wp[(size_t)c * K + k] = w[(size_t)(g * H_ + h) * K + k];
}
__global__ void permute_b(const float* __restrict__ b, float* __restrict__ bp)
{
    int c = blockIdx.x * 256 + threadIdx.x;
    if (c < G3_) bp[c] = b[(c % 3) * H_ + c / 3];
}
__global__ void zero_kernel(float* __restrict__ p, int n)
{
    int i = blockIdx.x * blockDim.x + threadIdx.x;
    if (i < n) p[i] = 0.f;
}

__global__ __launch_bounds__(256)
void ln_silu(const float* __restrict__ z,
             const float* __restrict__ lng,
             const float* __restrict__ lnb,
             float* __restrict__ out)
{
    __shared__ float red[256];
    int b = blockIdx.x, tid = threadIdx.x;
    const float* row = z + (size_t)b * H_;
    float s = 0.f, s2 = 0.f;
    for (int i = tid; i < H_; i += 256) { float v = row[i]; s += v; s2 += v * v; }
    red[tid] = s; __syncthreads();
    for (int o = 128; o > 0; o >>= 1) { if (tid < o) red[tid] += red[tid + o]; __syncthreads(); }
    float mu = red[0] / H_;
    __syncthreads();
    red[tid] = s2; __syncthreads();
    for (int o = 128; o > 0; o >>= 1) { if (tid < o) red[tid] += red[tid + o]; __syncthreads(); }
    float var = red[0] / H_ - mu * mu;
    float inv = rsqrtf(var + 1e-5f);
    for (int i = tid; i < H_; i += 256) {
        float y = (row[i] - mu) * inv * lng[i] + lnb[i];
        out[(size_t)b * H_ + i] = y / (1.f + expf(-y));
    }
}

__global__ __launch_bounds__(512)
void softmax_rebalance(const float* __restrict__ scores,
                       float* __restrict__ out)
{
    __shared__ float red[512];
    int b = blockIdx.x, tid = threadIdx.x;
    float s = (tid < N_) ? scores[(size_t)b * N_ + tid] : -INFINITY;
    if (s < 0.f) s = -INFINITY;
    red[tid] = s; __syncthreads();
    for (int o = 256; o > 0; o >>= 1) { if (tid < o) red[tid] = fmaxf(red[tid], red[tid + o]); __syncthreads(); }
    float m = red[0]; __syncthreads();
    float e = (tid < N_) ? expf(s - m) : 0.f;
    red[tid] = e; __syncthreads();
    for (int o = 256; o > 0; o >>= 1) { if (tid < o) red[tid] += red[tid + o]; __syncthreads(); }
    float S = red[0]; __syncthreads();
    float w = e / S;
    w = fminf(fmaxf(w, 0.0f), 0.1f);
    for (int it = 0; it < 20; it++) {
        red[tid] = (tid < N_) ? w : 0.f; __syncthreads();
        for (int o = 256; o > 0; o >>= 1) { if (tid < o) red[tid] += red[tid + o]; __syncthreads(); }
        float tot = red[0]; __syncthreads();
        float excess = tot - 1.0f;
        bool  active = excess > 1e-6f;
        float sur = fmaxf(w - 0.1f, 0.f);
        red[tid] = (tid < N_) ? sur : 0.f; __syncthreads();
        for (int o = 256; o > 0; o >>= 1) { if (tid < o) red[tid] += red[tid + o]; __syncthreads(); }
        float totsur = red[0]; __syncthreads();
        float upd = (totsur > 0.f)
                  ? w - sur / fmaxf(totsur, 1e-12f) * excess
                  : w - excess / (float)N_;
        upd = fminf(fmaxf(upd, 0.0f), 0.1f);
        if (active) w = upd;
    }
    if (tid < N_) out[(size_t)b * N_ + tid] = w;
}

// ===================== orchestration =====================
extern "C" void kernel_launch(void* const* d_in, const int* in_sizes, int n_in,
                              void* d_out, int out_size)
{
    const float* x     = (const float*)d_in[0];
    const float* w_ih0 = (const float*)d_in[1];
    const float* w_hh0 = (const float*)d_in[2];
    const float* b_ih0 = (const float*)d_in[3];
    const float* b_hh0 = (const float*)d_in[4];
    const float* w_ih1 = (const float*)d_in[5];
    const float* w_hh1 = (const float*)d_in[6];
    const float* b_ih1 = (const float*)d_in[7];
    const float* b_hh1 = (const float*)d_in[8];
    const float* w1    = (const float*)d_in[9];
    const float* b1    = (const float*)d_in[10];
    const float* ln_g  = (const float*)d_in[11];
    const float* ln_b  = (const float*)d_in[12];
    const float* w2    = (const float*)d_in[13];
    const float* b2    = (const float*)d_in[14];
    float* out = (float*)d_out;

    void* p;
    float *xproj, *seq, *h0, *h1, *z, *za, *scores;
    float *wih0p, *whh0p, *wih1p, *whh1p, *bih0p, *bhh0p, *bih1p, *bhh1p;
    cudaGetSymbolAddress(&p, g_xproj);  xproj  = (float*)p;
    cudaGetSymbolAddress(&p, g_seq);    seq    = (float*)p;
    cudaGetSymbolAddress(&p, g_h0);     h0     = (float*)p;
    cudaGetSymbolAddress(&p, g_h1);     h1     = (float*)p;
    cudaGetSymbolAddress(&p, g_z);      z      = (float*)p;
    cudaGetSymbolAddress(&p, g_za);     za     = (float*)p;
    cudaGetSymbolAddress(&p, g_scores); scores = (float*)p;
    cudaGetSymbolAddress(&p, g_wih0p);  wih0p  = (float*)p;
    cudaGetSymbolAddress(&p, g_whh0p);  whh0p  = (float*)p;
    cudaGetSymbolAddress(&p, g_wih1p);  wih1p  = (float*)p;
    cudaGetSymbolAddress(&p, g_whh1p);  whh1p  = (float*)p;
    cudaGetSymbolAddress(&p, g_bih0p);  bih0p  = (float*)p;
    cudaGetSymbolAddress(&p, g_bhh0p);  bhh0p  = (float*)p;
    cudaGetSymbolAddress(&p, g_bih1p);  bih1p  = (float*)p;
    cudaGetSymbolAddress(&p, g_bhh1p);  bhh1p  = (float*)p;

    // permute weights/biases into gate-interleaved layout (h*3+g)
    permute_w<<<dim3((N_ + 255) / 256, G3_), 256>>>(w_ih0, wih0p, N_);
    permute_w<<<dim3((H_ + 255) / 256, G3_), 256>>>(w_hh0, whh0p, H_);
    permute_w<<<dim3((H_ + 255) / 256, G3_), 256>>>(w_ih1, wih1p, H_);
    permute_w<<<dim3((H_ + 255) / 256, G3_), 256>>>(w_hh1, whh1p, H_);
    permute_b<<<(G3_ + 255) / 256, 256>>>(b_ih0, bih0p);
    permute_b<<<(G3_ + 255) / 256, 256>>>(b_hh0, bhh0p);
    permute_b<<<(G3_ + 255) / 256, 256>>>(b_ih1, bih1p);
    permute_b<<<(G3_ + 255) / 256, 256>>>(b_hh1, bhh1p);

    // layer 0 input projection: xproj = x @ wih0p^T + bih0p
    gemm_f2<<<dim3(G3_ / BN, BT_ / BM), NT>>>(x, wih0p, bih0p, xproj, BT_, G3_, N_);
    zero_kernel<<<(B_ * H_ + 255) / 256, 256>>>(h0, B_ * H_);

    // layer 0 recurrence (fused GEMM + gates)
    for (int t = 0; t < T_; t++) {
        float* hin  = (t & 1) ? h1 : h0;
        float* hout = (t & 1) ? h0 : h1;
        gru_step<<<dim3(G3_ / BN, B_ / BM), NT>>>(hin, whh0p, bhh0p, xproj, hout, seq, t);
    }

    // layer 1 input projection
    gemm_f2<<<dim3(G3_ / BN, BT_ / BM), NT>>>(seq, wih1p, bih1p, xproj, BT_, G3_, H_);
    zero_kernel<<<(B_ * H_ + 255) / 256, 256>>>(h0, B_ * H_);

    // layer 1 recurrence
    for (int t = 0; t < T_; t++) {
        float* hin  = (t & 1) ? h1 : h0;
        float* hout = (t & 1) ? h0 : h1;
        gru_step<<<dim3(G3_ / BN, B_ / BM), NT>>>(hin, whh1p, bhh1p, xproj, hout, nullptr, t);
    }

    // head
    gemm_f2<<<dim3((H_ + BN - 1) / BN, B_ / BM), NT>>>(h0, w1, b1, z, B_, H_, H_);
    ln_silu<<<B_, 256>>>(z, ln_g, ln_b, za);
    gemm_f2<<<dim3((N_ + BN - 1) / BN, B_ / BM), NT>>>(za, w2, b2, scores, B_, N_, H_);
    softmax_rebalance<<<B_, 512>>>(scores, out);
}